// round 7
// baseline (speedup 1.0000x reference)
#include <cuda_runtime.h>
#include <cstdint>

#define NB 64
#define NO 10
#define NI 8000
#define ND 16
#define NE 8

#define ITILE 2
#define NTHR 512
#define NSTAGES (NI / ITILE)     // 4000 stages of 2 i's
#define NBLK 296                 // 2 blocks/SM resident (persistent)
#define STEPI (NBLK * ITILE)     // i0 advance per grid-stride step = 592

#define NWITEM (ITILE * NO * 32) // 640 W float4 per stage
#define NXITEM (ITILE * NB * 2)  // 256 x float4 per stage
#define WBUFB (NWITEM * 16)      // 10240 B per W buffer
#define XBUFB (NXITEM * 16)      // 4096 B per x buffer

// Scratch (no allocation allowed). g_s zeroed by the fused squash each pass,
// g_ticket reset by the last block -> graph replays are deterministic.
__device__ float g_s[NB * NO * ND] = {};
__device__ float g_v[NB * NO * ND] = {};
__device__ float g_vsum[NB * NO * ND] = {};
__device__ unsigned int g_ticket = 0;

// ---- f32x2 packed math (sm_10x; ptxas won't auto-fuse, must be PTX) ----
__device__ __forceinline__ unsigned long long f2mul(unsigned long long a, unsigned long long b) {
    unsigned long long d;
    asm("mul.rn.f32x2 %0, %1, %2;" : "=l"(d) : "l"(a), "l"(b));
    return d;
}
__device__ __forceinline__ unsigned long long f2fma(unsigned long long a, unsigned long long b, unsigned long long c) {
    unsigned long long d;
    asm("fma.rn.f32x2 %0, %1, %2, %3;" : "=l"(d) : "l"(a), "l"(b), "l"(c));
    return d;
}
__device__ __forceinline__ float f2hadd(unsigned long long a) {
    float lo, hi;
    asm("mov.b64 {%0, %1}, %2;" : "=f"(lo), "=f"(hi) : "l"(a));
    return lo + hi;
}

// ---- cp.async (LDGSTS) helpers ----
__device__ __forceinline__ void cp16(uint32_t dst, const void* src) {
    asm volatile("cp.async.ca.shared.global [%0], [%1], 16;" :: "r"(dst), "l"(src));
}
__device__ __forceinline__ void cp_commit() { asm volatile("cp.async.commit_group;"); }
template <int N>
__device__ __forceinline__ void cp_wait() { asm volatile("cp.async.wait_group %0;" :: "n"(N)); }
__device__ __forceinline__ uint32_t sptr(const void* p) {
    return (uint32_t)__cvta_generic_to_shared(p);
}

// One fused pass: recompute u_hat tile-by-tile (3-deep cp.async ring, hoisted
// address math, 1 barrier/stage), route, accumulate s in regs, flush with
// atomics; LAST block performs squash (fused epilogue).
// Thread layout: lane = d (16), grp = tid>>4 (32 groups); each thread covers
// batches b0=grp and b1=grp+32, so every staged W value feeds 2 batches.
template <int ITER>
__global__ void __launch_bounds__(NTHR, 2)
pass_kernel(const float* __restrict__ xg, const float* __restrict__ Wg,
            float* __restrict__ out)
{
    __shared__ float4 shW[3][NWITEM];  // 3 x 10 KB, (j,o): idx = e4*16 + d
    __shared__ float4 shx[3][NXITEM];  // 3 x 4 KB

    const int tid  = threadIdx.x;
    const int lane = tid & 15;   // d
    const int grp  = tid >> 4;   // 0..31
    const int b0 = grp, b1 = grp + 32;

    const bool s8 = (lane & 8) != 0;
    const bool s4 = (lane & 4) != 0;
    const bool s2 = (lane & 2) != 0;
    const bool s1 = (lane & 1) != 0;
    // lane g holds a[o(g)]; valid (non-duplicate) lanes for softmax denom:
    const bool validLane = (!s1) || (!s2 && !s4);

    float vr0[NO], vr1[NO];
    if (ITER >= 1) {
        const float* vin = (ITER == 1) ? g_v : g_vsum;
        #pragma unroll
        for (int o = 0; o < NO; o++) {
            vr0[o] = vin[(b0 * NO + o) * ND + lane];
            vr1[o] = vin[(b1 * NO + o) * ND + lane];
        }
    }

    unsigned long long accp0[NO], accp1[NO];  // ITER 0: packed accumulators
    float acc0[NO], acc1[NO];
    #pragma unroll
    for (int o = 0; o < NO; o++) {
        accp0[o] = 0ull; accp1[o] = 0ull; acc0[o] = 0.f; acc1[o] = 0.f;
    }

    const float4* Wf4 = (const float4*)Wg;
    const float4* xf4 = (const float4*)xg;
    const uint32_t swbase = sptr(&shW[0][0]);
    const uint32_t sxbase = sptr(&shx[0][0]);

    // ---- hoisted staging descriptors: 896 items, 512 threads -> <=2 each.
    // item A (all threads): W item t = tid (< 640).
    // item B (tid<384): t = tid+512 -> W if tid<128, x if 128<=tid<384.
    const int st0 = blockIdx.x;
    const int i00 = st0 * ITILE;

    const float4* srcA;
    uint32_t dstA0;
    {
        int t = tid;
        int j  = t / (NO * 32);
        int r  = t - j * (NO * 32);
        int o  = r >> 5;
        int qg = r & 31;                       // global: d*2 + e4
        int qs = ((qg & 1) << 4) | (qg >> 1);  // shared: e4*16 + d
        srcA  = Wf4 + ((size_t)o * NI + i00 + j) * 32 + qg;
        dstA0 = swbase + (uint32_t)((j * NO + o) * 32 + qs) * 16u;
    }
    const bool hasB = (tid < 384);
    const float4* srcB = Wf4;   // dummy init
    uint32_t dstB0 = swbase;
    int      srcStepB = 0;
    uint32_t bufStrB = 0;
    if (tid < 128) {            // W item t = tid+512 in [512,640)
        int t = tid + 512;
        int j  = t / (NO * 32);
        int r  = t - j * (NO * 32);
        int o  = r >> 5;
        int qg = r & 31;
        int qs = ((qg & 1) << 4) | (qg >> 1);
        srcB  = Wf4 + ((size_t)o * NI + i00 + j) * 32 + qg;
        dstB0 = swbase + (uint32_t)((j * NO + o) * 32 + qs) * 16u;
        srcStepB = 32 * STEPI;
        bufStrB  = WBUFB;
    } else if (tid < 384) {     // x item v = tid+512-640 in [0,256)
        int v = tid - 128;
        int j = v >> 7;
        int r = v & 127;
        int bb = r >> 1;
        int q  = r & 1;
        srcB  = xf4 + ((size_t)bb * NI + i00 + j) * 2 + q;
        dstB0 = sxbase + (uint32_t)((j * NB + bb) * 2 + q) * 16u;
        srcStepB = 2 * STEPI;
        bufStrB  = XBUFB;
    }

    auto issue = [&](int ib) {
        cp16(dstA0 + (uint32_t)ib * WBUFB, srcA);
        srcA += 32 * STEPI;
        if (hasB) {
            cp16(dstB0 + (uint32_t)ib * bufStrB, srcB);
            srcB += srcStepB;
        }
        cp_commit();
    };

    // prologue: fill ring slots 0 and 1
    issue(0);
    if (st0 + NBLK < NSTAGES) issue(1); else cp_commit();

    int parity = 0, inext = 2;
    for (int st = st0; st < NSTAGES; st += NBLK) {
        cp_wait<1>();        // current stage's group complete (<=1 pending)
        __syncthreads();     // all warps see staged data; prev compute done
        if (st + 2 * NBLK < NSTAGES) issue(inext); else cp_commit();
        inext = (inext + 1 == 3) ? 0 : inext + 1;

        const ulonglong2* shWc = reinterpret_cast<const ulonglong2*>(shW[parity]);
        const ulonglong2* shxc = reinterpret_cast<const ulonglong2*>(shx[parity]);

        #pragma unroll
        for (int j = 0; j < ITILE; j++) {
            ulonglong2 xa0 = shxc[(j * NB + b0) * 2 + 0];  // (e0,e1),(e2,e3)
            ulonglong2 xb0 = shxc[(j * NB + b0) * 2 + 1];  // (e4,e5),(e6,e7)
            ulonglong2 xa1 = shxc[(j * NB + b1) * 2 + 0];
            ulonglong2 xb1 = shxc[(j * NB + b1) * 2 + 1];

            if (ITER == 0) {
                #pragma unroll
                for (int o = 0; o < NO; o++) {
                    ulonglong2 wa = shWc[(j * NO + o) * 32 + lane];       // e0..3
                    ulonglong2 wb = shWc[(j * NO + o) * 32 + 16 + lane];  // e4..7
                    accp0[o] = f2fma(wa.x, xa0.x, accp0[o]);
                    accp0[o] = f2fma(wa.y, xa0.y, accp0[o]);
                    accp0[o] = f2fma(wb.x, xb0.x, accp0[o]);
                    accp0[o] = f2fma(wb.y, xb0.y, accp0[o]);
                    accp1[o] = f2fma(wa.x, xa1.x, accp1[o]);
                    accp1[o] = f2fma(wa.y, xa1.y, accp1[o]);
                    accp1[o] = f2fma(wb.x, xb1.x, accp1[o]);
                    accp1[o] = f2fma(wb.y, xb1.y, accp1[o]);
                }
            } else {
                float u0[NO], u1[NO];
                #pragma unroll
                for (int o = 0; o < NO; o++) {
                    ulonglong2 wa = shWc[(j * NO + o) * 32 + lane];
                    ulonglong2 wb = shWc[(j * NO + o) * 32 + 16 + lane];
                    unsigned long long t0 = f2mul(wa.x, xa0.x);
                    t0 = f2fma(wa.y, xa0.y, t0);
                    t0 = f2fma(wb.x, xb0.x, t0);
                    t0 = f2fma(wb.y, xb0.y, t0);
                    u0[o] = f2hadd(t0);
                    unsigned long long t1 = f2mul(wa.x, xa1.x);
                    t1 = f2fma(wa.y, xa1.y, t1);
                    t1 = f2fma(wb.x, xb1.x, t1);
                    t1 = f2fma(wb.y, xb1.y, t1);
                    u1[o] = f2hadd(t1);
                }

                #pragma unroll
                for (int bb = 0; bb < 2; bb++) {
                    const float* u  = bb ? u1 : u0;
                    const float* vr = bb ? vr1 : vr0;
                    float* acc = bb ? acc1 : acc0;

                    // pairing-tree reduction of p[o]=u[o]*vr[o] over 16 d-lanes
                    float p[NO];
                    #pragma unroll
                    for (int o = 0; o < NO; o++) p[o] = u[o] * vr[o];

                    float q[5];
                    #pragma unroll
                    for (int k = 0; k < 5; k++) {
                        float keep = s8 ? p[2 * k + 1] : p[2 * k];
                        float send = s8 ? p[2 * k] : p[2 * k + 1];
                        q[k] = keep + __shfl_xor_sync(0xffffffffu, send, 8, 16);
                    }
                    float r0, r1, r2;
                    {
                        float keep = s4 ? q[1] : q[0];
                        float send = s4 ? q[0] : q[1];
                        r0 = keep + __shfl_xor_sync(0xffffffffu, send, 4, 16);
                    }
                    {
                        float keep = s4 ? q[3] : q[2];
                        float send = s4 ? q[2] : q[3];
                        r1 = keep + __shfl_xor_sync(0xffffffffu, send, 4, 16);
                    }
                    r2 = q[4] + __shfl_xor_sync(0xffffffffu, q[4], 4, 16);
                    float t0, t1;
                    {
                        float keep = s2 ? r1 : r0;
                        float send = s2 ? r0 : r1;
                        t0 = keep + __shfl_xor_sync(0xffffffffu, send, 2, 16);
                    }
                    t1 = r2 + __shfl_xor_sync(0xffffffffu, r2, 2, 16);
                    float a;
                    {
                        float keep = s1 ? t1 : t0;
                        float send = s1 ? t0 : t1;
                        a = keep + __shfl_xor_sync(0xffffffffu, send, 1, 16);
                    }

                    // distributed softmax (logits tiny -> no max subtraction)
                    float e = __expf(a);
                    float m = validLane ? e : 0.f;
                    m += __shfl_xor_sync(0xffffffffu, m, 8, 16);
                    m += __shfl_xor_sync(0xffffffffu, m, 4, 16);
                    m += __shfl_xor_sync(0xffffffffu, m, 2, 16);
                    m += __shfl_xor_sync(0xffffffffu, m, 1, 16);
                    float c_self = __fdividef(e, m);

                    // broadcast c[o] from its owner lane, accumulate
                    // o -> lane: {0,8,4,12,2,10,6,14,1,9}
                    acc[0] = fmaf(__shfl_sync(0xffffffffu, c_self, 0, 16),  u[0], acc[0]);
                    acc[1] = fmaf(__shfl_sync(0xffffffffu, c_self, 8, 16),  u[1], acc[1]);
                    acc[2] = fmaf(__shfl_sync(0xffffffffu, c_self, 4, 16),  u[2], acc[2]);
                    acc[3] = fmaf(__shfl_sync(0xffffffffu, c_self, 12, 16), u[3], acc[3]);
                    acc[4] = fmaf(__shfl_sync(0xffffffffu, c_self, 2, 16),  u[4], acc[4]);
                    acc[5] = fmaf(__shfl_sync(0xffffffffu, c_self, 10, 16), u[5], acc[5]);
                    acc[6] = fmaf(__shfl_sync(0xffffffffu, c_self, 6, 16),  u[6], acc[6]);
                    acc[7] = fmaf(__shfl_sync(0xffffffffu, c_self, 14, 16), u[7], acc[7]);
                    acc[8] = fmaf(__shfl_sync(0xffffffffu, c_self, 1, 16),  u[8], acc[8]);
                    acc[9] = fmaf(__shfl_sync(0xffffffffu, c_self, 9, 16),  u[9], acc[9]);
                }
            }
        }

        parity = (parity + 1 == 3) ? 0 : parity + 1;
    }

    if (ITER == 0) {
        #pragma unroll
        for (int o = 0; o < NO; o++) {
            acc0[o] = f2hadd(accp0[o]);
            acc1[o] = f2hadd(accp1[o]);
        }
    }
    #pragma unroll
    for (int o = 0; o < NO; o++) {
        atomicAdd(&g_s[(b0 * NO + o) * ND + lane], acc0[o]);
        atomicAdd(&g_s[(b1 * NO + o) * ND + lane], acc1[o]);
    }

    // ---- fused squash: last block to finish does the epilogue ----
    __threadfence();
    __shared__ unsigned int lastFlag;
    if (tid == 0)
        lastFlag = (atomicAdd(&g_ticket, 1u) == (unsigned)(gridDim.x - 1)) ? 1u : 0u;
    __syncthreads();
    if (!lastFlag) return;
    __threadfence();  // acquire: all other blocks' atomics are visible

    const float prescale = (ITER == 0) ? 0.1f : 1.0f;
    #pragma unroll
    for (int k = 0; k < (NB * NO * ND) / NTHR; k++) {
        int idx = k * NTHR + tid;            // idx & 15 == lane (NTHR % 16 == 0)
        float val = g_s[idx] * prescale;
        g_s[idx] = 0.f;
        float n2 = val * val;
        n2 += __shfl_xor_sync(0xffffffffu, n2, 8, 16);
        n2 += __shfl_xor_sync(0xffffffffu, n2, 4, 16);
        n2 += __shfl_xor_sync(0xffffffffu, n2, 2, 16);
        n2 += __shfl_xor_sync(0xffffffffu, n2, 1, 16);
        float norm  = sqrtf(n2);
        float scale = n2 / ((1.f + n2) * (norm + 1e-8f));
        float v = scale * val;
        if (ITER == 0)      { g_v[idx] = v; g_vsum[idx] = v; }
        else if (ITER == 1) { g_v[idx] = v; g_vsum[idx] += v; }
        else                { out[idx] = v; }
    }
    if (tid == 0) g_ticket = 0;  // reset for next pass / next graph replay
}

extern "C" void kernel_launch(void* const* d_in, const int* in_sizes, int n_in,
                              void* d_out, int out_size)
{
    const float* x = (const float*)d_in[0];  // [64, 8000, 8]
    const float* W = (const float*)d_in[1];  // [10, 8000, 16, 8]
    float* out = (float*)d_out;              // [64, 10, 16]

    pass_kernel<0><<<NBLK, NTHR>>>(x, W, out);  // uniform c=0.1 (in prescale)
    pass_kernel<1><<<NBLK, NTHR>>>(x, W, out);  // c = softmax_o(u.v0)
    pass_kernel<2><<<NBLK, NTHR>>>(x, W, out);  // c = softmax_o(u.(v0+v1))
}

// round 8
// speedup vs baseline: 1.1957x; 1.1957x over previous
#include <cuda_runtime.h>
#include <cstdint>

#define NB 64
#define NO 10
#define NI 8000
#define ND 16
#define NE 8

#define ITILE 2
#define NTHR 512
#define NSTAGES (NI / ITILE)     // 4000 stages of 2 i's

#define NWITEM (ITILE * NO * 32) // 640 W float4 per stage
#define NXITEM (ITILE * NB * 2)  // 256 x float4 per stage
#define WBUFB (NWITEM * 16)      // 10240 B per W buffer
#define XBUFB (NXITEM * 16)      // 4096 B per x buffer

// per-pass launch geometry: pass0 runs 2 blocks/SM (64 regs is enough, no
// spills); routed passes need ~95 regs -> 1 block/SM, one full wave of 148.
#define NBLK0 296
#define NBLKR 148

// Scratch (no allocation allowed). g_s zeroed by the fused squash each pass,
// g_ticket reset by the last block -> graph replays are deterministic.
__device__ float g_s[NB * NO * ND] = {};
__device__ float g_v[NB * NO * ND] = {};
__device__ float g_vsum[NB * NO * ND] = {};
__device__ unsigned int g_ticket = 0;

// ---- f32x2 packed math (sm_10x; ptxas won't auto-fuse, must be PTX) ----
__device__ __forceinline__ unsigned long long f2mul(unsigned long long a, unsigned long long b) {
    unsigned long long d;
    asm("mul.rn.f32x2 %0, %1, %2;" : "=l"(d) : "l"(a), "l"(b));
    return d;
}
__device__ __forceinline__ unsigned long long f2fma(unsigned long long a, unsigned long long b, unsigned long long c) {
    unsigned long long d;
    asm("fma.rn.f32x2 %0, %1, %2, %3;" : "=l"(d) : "l"(a), "l"(b), "l"(c));
    return d;
}
__device__ __forceinline__ float f2hadd(unsigned long long a) {
    float lo, hi;
    asm("mov.b64 {%0, %1}, %2;" : "=f"(lo), "=f"(hi) : "l"(a));
    return lo + hi;
}

// ---- cp.async (LDGSTS) helpers ----
__device__ __forceinline__ void cp16(uint32_t dst, const void* src) {
    asm volatile("cp.async.ca.shared.global [%0], [%1], 16;" :: "r"(dst), "l"(src));
}
__device__ __forceinline__ void cp_commit() { asm volatile("cp.async.commit_group;"); }
template <int N>
__device__ __forceinline__ void cp_wait() { asm volatile("cp.async.wait_group %0;" :: "n"(N)); }
__device__ __forceinline__ uint32_t sptr(const void* p) {
    return (uint32_t)__cvta_generic_to_shared(p);
}

// One fused pass: recompute u_hat tile-by-tile (3-deep cp.async ring, hoisted
// address math, 1 barrier/stage), route, accumulate s in regs, flush with
// atomics; LAST block performs squash (fused epilogue).
// Thread layout: lane = d (16), grp = tid>>4 (32 groups); each thread covers
// batches b0=grp and b1=grp+32, so every staged W value feeds 2 batches.
// ITER 0 gets 2 blocks/SM (fits 64 regs); ITER>=1 gets 1 block/SM so ptxas
// can use ~95 regs without spilling to local memory.
template <int ITER>
__global__ void __launch_bounds__(NTHR, (ITER == 0) ? 2 : 1)
pass_kernel(const float* __restrict__ xg, const float* __restrict__ Wg,
            float* __restrict__ out)
{
    constexpr int NBLK  = (ITER == 0) ? NBLK0 : NBLKR;
    constexpr int STEPI = NBLK * ITILE;   // i0 advance per grid-stride step

    __shared__ float4 shW[3][NWITEM];  // 3 x 10 KB, (j,o): idx = e4*16 + d
    __shared__ float4 shx[3][NXITEM];  // 3 x 4 KB

    const int tid  = threadIdx.x;
    const int lane = tid & 15;   // d
    const int grp  = tid >> 4;   // 0..31
    const int b0 = grp, b1 = grp + 32;

    const bool s8 = (lane & 8) != 0;
    const bool s4 = (lane & 4) != 0;
    const bool s2 = (lane & 2) != 0;
    const bool s1 = (lane & 1) != 0;
    // lane g holds a[o(g)]; valid (non-duplicate) lanes for softmax denom:
    const bool validLane = (!s1) || (!s2 && !s4);

    float vr0[NO], vr1[NO];
    if (ITER >= 1) {
        const float* vin = (ITER == 1) ? g_v : g_vsum;
        #pragma unroll
        for (int o = 0; o < NO; o++) {
            vr0[o] = vin[(b0 * NO + o) * ND + lane];
            vr1[o] = vin[(b1 * NO + o) * ND + lane];
        }
    }

    unsigned long long accp0[NO], accp1[NO];  // ITER 0: packed accumulators
    float acc0[NO], acc1[NO];
    #pragma unroll
    for (int o = 0; o < NO; o++) {
        accp0[o] = 0ull; accp1[o] = 0ull; acc0[o] = 0.f; acc1[o] = 0.f;
    }

    const float4* Wf4 = (const float4*)Wg;
    const float4* xf4 = (const float4*)xg;
    const uint32_t swbase = sptr(&shW[0][0]);
    const uint32_t sxbase = sptr(&shx[0][0]);

    // ---- hoisted staging descriptors: 896 items, 512 threads -> <=2 each.
    // item A (all threads): W item t = tid (< 640).
    // item B (tid<384): t = tid+512 -> W if tid<128, x if 128<=tid<384.
    const int st0 = blockIdx.x;
    const int i00 = st0 * ITILE;

    const float4* srcA;
    uint32_t dstA0;
    {
        int t = tid;
        int j  = t / (NO * 32);
        int r  = t - j * (NO * 32);
        int o  = r >> 5;
        int qg = r & 31;                       // global: d*2 + e4
        int qs = ((qg & 1) << 4) | (qg >> 1);  // shared: e4*16 + d
        srcA  = Wf4 + ((size_t)o * NI + i00 + j) * 32 + qg;
        dstA0 = swbase + (uint32_t)((j * NO + o) * 32 + qs) * 16u;
    }
    const bool hasB = (tid < 384);
    const float4* srcB = Wf4;   // dummy init
    uint32_t dstB0 = swbase;
    int      srcStepB = 0;
    uint32_t bufStrB = 0;
    if (tid < 128) {            // W item t = tid+512 in [512,640)
        int t = tid + 512;
        int j  = t / (NO * 32);
        int r  = t - j * (NO * 32);
        int o  = r >> 5;
        int qg = r & 31;
        int qs = ((qg & 1) << 4) | (qg >> 1);
        srcB  = Wf4 + ((size_t)o * NI + i00 + j) * 32 + qg;
        dstB0 = swbase + (uint32_t)((j * NO + o) * 32 + qs) * 16u;
        srcStepB = 32 * STEPI;
        bufStrB  = WBUFB;
    } else if (tid < 384) {     // x item v = tid+512-640 in [0,256)
        int v = tid - 128;
        int j = v >> 7;
        int r = v & 127;
        int bb = r >> 1;
        int q  = r & 1;
        srcB  = xf4 + ((size_t)bb * NI + i00 + j) * 2 + q;
        dstB0 = sxbase + (uint32_t)((j * NB + bb) * 2 + q) * 16u;
        srcStepB = 2 * STEPI;
        bufStrB  = XBUFB;
    }

    auto issue = [&](int ib) {
        cp16(dstA0 + (uint32_t)ib * WBUFB, srcA);
        srcA += 32 * STEPI;
        if (hasB) {
            cp16(dstB0 + (uint32_t)ib * bufStrB, srcB);
            srcB += srcStepB;
        }
        cp_commit();
    };

    // prologue: fill ring slots 0 and 1
    issue(0);
    if (st0 + NBLK < NSTAGES) issue(1); else cp_commit();

    int parity = 0, inext = 2;
    for (int st = st0; st < NSTAGES; st += NBLK) {
        cp_wait<1>();        // current stage's group complete (<=1 pending)
        __syncthreads();     // all warps see staged data; prev compute done
        if (st + 2 * NBLK < NSTAGES) issue(inext); else cp_commit();
        inext = (inext + 1 == 3) ? 0 : inext + 1;

        const ulonglong2* shWc = reinterpret_cast<const ulonglong2*>(shW[parity]);
        const ulonglong2* shxc = reinterpret_cast<const ulonglong2*>(shx[parity]);

        #pragma unroll
        for (int j = 0; j < ITILE; j++) {
            ulonglong2 xa0 = shxc[(j * NB + b0) * 2 + 0];  // (e0,e1),(e2,e3)
            ulonglong2 xb0 = shxc[(j * NB + b0) * 2 + 1];  // (e4,e5),(e6,e7)
            ulonglong2 xa1 = shxc[(j * NB + b1) * 2 + 0];
            ulonglong2 xb1 = shxc[(j * NB + b1) * 2 + 1];

            if (ITER == 0) {
                #pragma unroll
                for (int o = 0; o < NO; o++) {
                    ulonglong2 wa = shWc[(j * NO + o) * 32 + lane];       // e0..3
                    ulonglong2 wb = shWc[(j * NO + o) * 32 + 16 + lane];  // e4..7
                    accp0[o] = f2fma(wa.x, xa0.x, accp0[o]);
                    accp0[o] = f2fma(wa.y, xa0.y, accp0[o]);
                    accp0[o] = f2fma(wb.x, xb0.x, accp0[o]);
                    accp0[o] = f2fma(wb.y, xb0.y, accp0[o]);
                    accp1[o] = f2fma(wa.x, xa1.x, accp1[o]);
                    accp1[o] = f2fma(wa.y, xa1.y, accp1[o]);
                    accp1[o] = f2fma(wb.x, xb1.x, accp1[o]);
                    accp1[o] = f2fma(wb.y, xb1.y, accp1[o]);
                }
            } else {
                float u0[NO], u1[NO];
                #pragma unroll
                for (int o = 0; o < NO; o++) {
                    ulonglong2 wa = shWc[(j * NO + o) * 32 + lane];
                    ulonglong2 wb = shWc[(j * NO + o) * 32 + 16 + lane];
                    unsigned long long t0 = f2mul(wa.x, xa0.x);
                    t0 = f2fma(wa.y, xa0.y, t0);
                    t0 = f2fma(wb.x, xb0.x, t0);
                    t0 = f2fma(wb.y, xb0.y, t0);
                    u0[o] = f2hadd(t0);
                    unsigned long long t1 = f2mul(wa.x, xa1.x);
                    t1 = f2fma(wa.y, xa1.y, t1);
                    t1 = f2fma(wb.x, xb1.x, t1);
                    t1 = f2fma(wb.y, xb1.y, t1);
                    u1[o] = f2hadd(t1);
                }

                #pragma unroll
                for (int bb = 0; bb < 2; bb++) {
                    const float* u  = bb ? u1 : u0;
                    const float* vr = bb ? vr1 : vr0;
                    float* acc = bb ? acc1 : acc0;

                    // pairing-tree reduction of p[o]=u[o]*vr[o] over 16 d-lanes
                    float p[NO];
                    #pragma unroll
                    for (int o = 0; o < NO; o++) p[o] = u[o] * vr[o];

                    float q[5];
                    #pragma unroll
                    for (int k = 0; k < 5; k++) {
                        float keep = s8 ? p[2 * k + 1] : p[2 * k];
                        float send = s8 ? p[2 * k] : p[2 * k + 1];
                        q[k] = keep + __shfl_xor_sync(0xffffffffu, send, 8, 16);
                    }
                    float r0, r1, r2;
                    {
                        float keep = s4 ? q[1] : q[0];
                        float send = s4 ? q[0] : q[1];
                        r0 = keep + __shfl_xor_sync(0xffffffffu, send, 4, 16);
                    }
                    {
                        float keep = s4 ? q[3] : q[2];
                        float send = s4 ? q[2] : q[3];
                        r1 = keep + __shfl_xor_sync(0xffffffffu, send, 4, 16);
                    }
                    r2 = q[4] + __shfl_xor_sync(0xffffffffu, q[4], 4, 16);
                    float t0, t1;
                    {
                        float keep = s2 ? r1 : r0;
                        float send = s2 ? r0 : r1;
                        t0 = keep + __shfl_xor_sync(0xffffffffu, send, 2, 16);
                    }
                    t1 = r2 + __shfl_xor_sync(0xffffffffu, r2, 2, 16);
                    float a;
                    {
                        float keep = s1 ? t1 : t0;
                        float send = s1 ? t0 : t1;
                        a = keep + __shfl_xor_sync(0xffffffffu, send, 1, 16);
                    }

                    // distributed softmax (logits tiny -> no max subtraction)
                    float e = __expf(a);
                    float m = validLane ? e : 0.f;
                    m += __shfl_xor_sync(0xffffffffu, m, 8, 16);
                    m += __shfl_xor_sync(0xffffffffu, m, 4, 16);
                    m += __shfl_xor_sync(0xffffffffu, m, 2, 16);
                    m += __shfl_xor_sync(0xffffffffu, m, 1, 16);
                    float c_self = __fdividef(e, m);

                    // broadcast c[o] from its owner lane, accumulate
                    // o -> lane: {0,8,4,12,2,10,6,14,1,9}
                    acc[0] = fmaf(__shfl_sync(0xffffffffu, c_self, 0, 16),  u[0], acc[0]);
                    acc[1] = fmaf(__shfl_sync(0xffffffffu, c_self, 8, 16),  u[1], acc[1]);
                    acc[2] = fmaf(__shfl_sync(0xffffffffu, c_self, 4, 16),  u[2], acc[2]);
                    acc[3] = fmaf(__shfl_sync(0xffffffffu, c_self, 12, 16), u[3], acc[3]);
                    acc[4] = fmaf(__shfl_sync(0xffffffffu, c_self, 2, 16),  u[4], acc[4]);
                    acc[5] = fmaf(__shfl_sync(0xffffffffu, c_self, 10, 16), u[5], acc[5]);
                    acc[6] = fmaf(__shfl_sync(0xffffffffu, c_self, 6, 16),  u[6], acc[6]);
                    acc[7] = fmaf(__shfl_sync(0xffffffffu, c_self, 14, 16), u[7], acc[7]);
                    acc[8] = fmaf(__shfl_sync(0xffffffffu, c_self, 1, 16),  u[8], acc[8]);
                    acc[9] = fmaf(__shfl_sync(0xffffffffu, c_self, 9, 16),  u[9], acc[9]);
                }
            }
        }

        parity = (parity + 1 == 3) ? 0 : parity + 1;
    }

    if (ITER == 0) {
        #pragma unroll
        for (int o = 0; o < NO; o++) {
            acc0[o] = f2hadd(accp0[o]);
            acc1[o] = f2hadd(accp1[o]);
        }
    }
    #pragma unroll
    for (int o = 0; o < NO; o++) {
        atomicAdd(&g_s[(b0 * NO + o) * ND + lane], acc0[o]);
        atomicAdd(&g_s[(b1 * NO + o) * ND + lane], acc1[o]);
    }

    // ---- fused squash: last block to finish does the epilogue ----
    __threadfence();
    __shared__ unsigned int lastFlag;
    if (tid == 0)
        lastFlag = (atomicAdd(&g_ticket, 1u) == (unsigned)(gridDim.x - 1)) ? 1u : 0u;
    __syncthreads();
    if (!lastFlag) return;
    __threadfence();  // acquire: all other blocks' atomics are visible

    const float prescale = (ITER == 0) ? 0.1f : 1.0f;
    #pragma unroll
    for (int k = 0; k < (NB * NO * ND) / NTHR; k++) {
        int idx = k * NTHR + tid;            // idx & 15 == lane (NTHR % 16 == 0)
        float val = g_s[idx] * prescale;
        g_s[idx] = 0.f;
        float n2 = val * val;
        n2 += __shfl_xor_sync(0xffffffffu, n2, 8, 16);
        n2 += __shfl_xor_sync(0xffffffffu, n2, 4, 16);
        n2 += __shfl_xor_sync(0xffffffffu, n2, 2, 16);
        n2 += __shfl_xor_sync(0xffffffffu, n2, 1, 16);
        float norm  = sqrtf(n2);
        float scale = n2 / ((1.f + n2) * (norm + 1e-8f));
        float v = scale * val;
        if (ITER == 0)      { g_v[idx] = v; g_vsum[idx] = v; }
        else if (ITER == 1) { g_v[idx] = v; g_vsum[idx] += v; }
        else                { out[idx] = v; }
    }
    if (tid == 0) g_ticket = 0;  // reset for next pass / next graph replay
}

extern "C" void kernel_launch(void* const* d_in, const int* in_sizes, int n_in,
                              void* d_out, int out_size)
{
    const float* x = (const float*)d_in[0];  // [64, 8000, 8]
    const float* W = (const float*)d_in[1];  // [10, 8000, 16, 8]
    float* out = (float*)d_out;              // [64, 10, 16]

    pass_kernel<0><<<NBLK0, NTHR>>>(x, W, out);  // uniform c=0.1 (in prescale)
    pass_kernel<1><<<NBLKR, NTHR>>>(x, W, out);  // c = softmax_o(u.v0)
    pass_kernel<2><<<NBLKR, NTHR>>>(x, W, out);  // c = softmax_o(u.(v0+v1))
}

// round 9
// speedup vs baseline: 1.2801x; 1.0706x over previous
#include <cuda_runtime.h>
#include <cstdint>

#define NB 64
#define NO 10
#define NI 8000
#define ND 16
#define NE 8

#define ITILE 2
#define NTHR 512
#define NSTAGES (NI / ITILE)     // 4000 stages of 2 i's

#define NWITEM (ITILE * NO * 32) // 640 W float4 per stage
#define NXITEM (ITILE * NB * 2)  // 256 x float4 per stage
#define WBUFB (NWITEM * 16)      // 10240 B per W buffer
#define XBUFB (NXITEM * 16)      // 4096 B per x buffer

// All passes now run 1 block/SM, one full wave of 148 blocks.
// pass0 uses ~90 regs (4-batch quad layout), routed ~95 regs.
#define NBLK 148
#define STEPI (NBLK * ITILE)     // i0 advance per grid-stride step = 296

// Scratch (no allocation allowed). g_s zeroed by the fused squash each pass,
// g_ticket reset by the last block -> graph replays are deterministic.
__device__ float g_s[NB * NO * ND] = {};
__device__ float g_v[NB * NO * ND] = {};
__device__ float g_vsum[NB * NO * ND] = {};
__device__ unsigned int g_ticket = 0;

// ---- f32x2 packed math (sm_10x; ptxas won't auto-fuse, must be PTX) ----
__device__ __forceinline__ unsigned long long f2mul(unsigned long long a, unsigned long long b) {
    unsigned long long d;
    asm("mul.rn.f32x2 %0, %1, %2;" : "=l"(d) : "l"(a), "l"(b));
    return d;
}
__device__ __forceinline__ unsigned long long f2fma(unsigned long long a, unsigned long long b, unsigned long long c) {
    unsigned long long d;
    asm("fma.rn.f32x2 %0, %1, %2, %3;" : "=l"(d) : "l"(a), "l"(b), "l"(c));
    return d;
}
__device__ __forceinline__ float f2hadd(unsigned long long a) {
    float lo, hi;
    asm("mov.b64 {%0, %1}, %2;" : "=f"(lo), "=f"(hi) : "l"(a));
    return lo + hi;
}

// ---- cp.async (LDGSTS) helpers ----
__device__ __forceinline__ void cp16(uint32_t dst, const void* src) {
    asm volatile("cp.async.ca.shared.global [%0], [%1], 16;" :: "r"(dst), "l"(src));
}
__device__ __forceinline__ void cp_commit() { asm volatile("cp.async.commit_group;"); }
template <int N>
__device__ __forceinline__ void cp_wait() { asm volatile("cp.async.wait_group %0;" :: "n"(N)); }
__device__ __forceinline__ uint32_t sptr(const void* p) {
    return (uint32_t)__cvta_generic_to_shared(p);
}

// ---- shared staging descriptor (same smem image for all passes) ----
// shW per (j,o): 32 float4, idx qs = e4*16 + d. shx per (j,b): 2 float4.
struct Stager {
    const float4* srcA;
    const float4* srcB;
    uint32_t dstA0, dstB0, bufStrB;
    int srcStepB;
    bool hasB;

    __device__ __forceinline__ void init(int tid, int i00,
                                         const float4* Wf4, const float4* xf4,
                                         uint32_t swbase, uint32_t sxbase) {
        {
            int t = tid;                           // W item < 640
            int j  = t / (NO * 32);
            int r  = t - j * (NO * 32);
            int o  = r >> 5;
            int qg = r & 31;                       // global: d*2 + e4
            int qs = ((qg & 1) << 4) | (qg >> 1);  // shared: e4*16 + d
            srcA  = Wf4 + ((size_t)o * NI + i00 + j) * 32 + qg;
            dstA0 = swbase + (uint32_t)((j * NO + o) * 32 + qs) * 16u;
        }
        hasB = (tid < 384);
        srcB = Wf4; dstB0 = swbase; srcStepB = 0; bufStrB = 0;
        if (tid < 128) {            // W item t = tid+512 in [512,640)
            int t = tid + 512;
            int j  = t / (NO * 32);
            int r  = t - j * (NO * 32);
            int o  = r >> 5;
            int qg = r & 31;
            int qs = ((qg & 1) << 4) | (qg >> 1);
            srcB  = Wf4 + ((size_t)o * NI + i00 + j) * 32 + qg;
            dstB0 = swbase + (uint32_t)((j * NO + o) * 32 + qs) * 16u;
            srcStepB = 32 * STEPI;
            bufStrB  = WBUFB;
        } else if (tid < 384) {     // x item v = tid-128 in [0,256)
            int v = tid - 128;
            int j = v >> 7;
            int r = v & 127;
            int bb = r >> 1;
            int q  = r & 1;
            srcB  = xf4 + ((size_t)bb * NI + i00 + j) * 2 + q;
            dstB0 = sxbase + (uint32_t)((j * NB + bb) * 2 + q) * 16u;
            srcStepB = 2 * STEPI;
            bufStrB  = XBUFB;
        }
    }
    __device__ __forceinline__ void issue(int ib) {
        cp16(dstA0 + (uint32_t)ib * WBUFB, srcA);
        srcA += 32 * STEPI;
        if (hasB) {
            cp16(dstB0 + (uint32_t)ib * bufStrB, srcB);
            srcB += srcStepB;
        }
        cp_commit();
    }
};

// ---- fused squash epilogue (last block), shared by all passes ----
template <int ITER>
__device__ __forceinline__ void squash_epilogue(int tid, float* __restrict__ out)
{
    __threadfence();
    __shared__ unsigned int lastFlag;
    if (tid == 0)
        lastFlag = (atomicAdd(&g_ticket, 1u) == (unsigned)(NBLK - 1)) ? 1u : 0u;
    __syncthreads();
    if (!lastFlag) return;
    __threadfence();  // acquire: all other blocks' atomics are visible

    const float prescale = (ITER == 0) ? 0.1f : 1.0f;
    #pragma unroll
    for (int k = 0; k < (NB * NO * ND) / NTHR; k++) {
        int idx = k * NTHR + tid;            // idx & 15 == d-lane
        float val = g_s[idx] * prescale;
        g_s[idx] = 0.f;
        float n2 = val * val;
        n2 += __shfl_xor_sync(0xffffffffu, n2, 8, 16);
        n2 += __shfl_xor_sync(0xffffffffu, n2, 4, 16);
        n2 += __shfl_xor_sync(0xffffffffu, n2, 2, 16);
        n2 += __shfl_xor_sync(0xffffffffu, n2, 1, 16);
        float norm  = sqrtf(n2);
        float scale = n2 / ((1.f + n2) * (norm + 1e-8f));
        float v = scale * val;
        if (ITER == 0)      { g_v[idx] = v; g_vsum[idx] = v; }
        else if (ITER == 1) { g_v[idx] = v; g_vsum[idx] += v; }
        else                { out[idx] = v; }
    }
    if (tid == 0) g_ticket = 0;  // reset for next pass / next graph replay
}

// ============ PASS 0: pure split-K GEMM, (4 batch, 5 o) per thread ============
// Warp = one batch-quad; half-warp 0 handles o 0-4, half-warp 1 handles o 5-9.
// All 32 lanes read DISTINCT W addresses (no duplicate crossbar phases) and
// every staged W value feeds 4 batches -> W LDS traffic halves vs (2b,10o).
__global__ void __launch_bounds__(NTHR, 1)
pass0_kernel(const float* __restrict__ xg, const float* __restrict__ Wg,
             float* __restrict__ out)
{
    __shared__ float4 shW[3][NWITEM];  // 3 x 10 KB
    __shared__ float4 shx[3][NXITEM];  // 3 x 4 KB

    const int tid  = threadIdx.x;
    const int lane = tid & 15;        // d
    const int grp  = tid >> 4;        // 0..31
    const int quad = grp >> 1;        // 0..15 -> batches 4q..4q+3
    const int ob   = (grp & 1) * 5;   // o-half base: 0 or 5

    unsigned long long accp[4][5];
    #pragma unroll
    for (int bb = 0; bb < 4; bb++)
        #pragma unroll
        for (int o = 0; o < 5; o++) accp[bb][o] = 0ull;

    const float4* Wf4 = (const float4*)Wg;
    const float4* xf4 = (const float4*)xg;

    Stager sg;
    sg.init(tid, blockIdx.x * ITILE, Wf4, xf4, sptr(&shW[0][0]), sptr(&shx[0][0]));

    const int st0 = blockIdx.x;
    sg.issue(0);
    if (st0 + NBLK < NSTAGES) sg.issue(1); else cp_commit();

    int parity = 0, inext = 2;
    for (int st = st0; st < NSTAGES; st += NBLK) {
        cp_wait<1>();
        __syncthreads();
        if (st + 2 * NBLK < NSTAGES) sg.issue(inext); else cp_commit();
        inext = (inext + 1 == 3) ? 0 : inext + 1;

        const ulonglong2* shWc = reinterpret_cast<const ulonglong2*>(shW[parity]);
        const ulonglong2* shxc = reinterpret_cast<const ulonglong2*>(shx[parity]);

        #pragma unroll
        for (int j = 0; j < ITILE; j++) {
            ulonglong2 xa[4], xb[4];
            #pragma unroll
            for (int bb = 0; bb < 4; bb++) {
                xa[bb] = shxc[(j * NB + quad * 4 + bb) * 2 + 0];  // e0..3
                xb[bb] = shxc[(j * NB + quad * 4 + bb) * 2 + 1];  // e4..7
            }
            #pragma unroll
            for (int o = 0; o < 5; o++) {
                const int og = ob + o;
                ulonglong2 wa = shWc[(j * NO + og) * 32 + lane];       // e0..3
                ulonglong2 wb = shWc[(j * NO + og) * 32 + 16 + lane];  // e4..7
                #pragma unroll
                for (int bb = 0; bb < 4; bb++) {
                    accp[bb][o] = f2fma(wa.x, xa[bb].x, accp[bb][o]);
                    accp[bb][o] = f2fma(wa.y, xa[bb].y, accp[bb][o]);
                    accp[bb][o] = f2fma(wb.x, xb[bb].x, accp[bb][o]);
                    accp[bb][o] = f2fma(wb.y, xb[bb].y, accp[bb][o]);
                }
            }
        }
        parity = (parity + 1 == 3) ? 0 : parity + 1;
    }

    #pragma unroll
    for (int bb = 0; bb < 4; bb++)
        #pragma unroll
        for (int o = 0; o < 5; o++)
            atomicAdd(&g_s[((quad * 4 + bb) * NO + ob + o) * ND + lane],
                      f2hadd(accp[bb][o]));

    squash_epilogue<0>(tid, out);
}

// ============ ROUTED PASSES (ITER 1/2): unchanged R7 structure ============
// Thread layout: lane = d (16), grp covers batches b0=grp, b1=grp+32.
template <int ITER>
__global__ void __launch_bounds__(NTHR, 1)
pass_kernel(const float* __restrict__ xg, const float* __restrict__ Wg,
            float* __restrict__ out)
{
    __shared__ float4 shW[3][NWITEM];
    __shared__ float4 shx[3][NXITEM];

    const int tid  = threadIdx.x;
    const int lane = tid & 15;   // d
    const int grp  = tid >> 4;   // 0..31
    const int b0 = grp, b1 = grp + 32;

    const bool s8 = (lane & 8) != 0;
    const bool s4 = (lane & 4) != 0;
    const bool s2 = (lane & 2) != 0;
    const bool s1 = (lane & 1) != 0;
    const bool validLane = (!s1) || (!s2 && !s4);

    float vr0[NO], vr1[NO];
    {
        const float* vin = (ITER == 1) ? g_v : g_vsum;
        #pragma unroll
        for (int o = 0; o < NO; o++) {
            vr0[o] = vin[(b0 * NO + o) * ND + lane];
            vr1[o] = vin[(b1 * NO + o) * ND + lane];
        }
    }

    float acc0[NO], acc1[NO];
    #pragma unroll
    for (int o = 0; o < NO; o++) { acc0[o] = 0.f; acc1[o] = 0.f; }

    const float4* Wf4 = (const float4*)Wg;
    const float4* xf4 = (const float4*)xg;

    Stager sg;
    sg.init(tid, blockIdx.x * ITILE, Wf4, xf4, sptr(&shW[0][0]), sptr(&shx[0][0]));

    const int st0 = blockIdx.x;
    sg.issue(0);
    if (st0 + NBLK < NSTAGES) sg.issue(1); else cp_commit();

    int parity = 0, inext = 2;
    for (int st = st0; st < NSTAGES; st += NBLK) {
        cp_wait<1>();
        __syncthreads();
        if (st + 2 * NBLK < NSTAGES) sg.issue(inext); else cp_commit();
        inext = (inext + 1 == 3) ? 0 : inext + 1;

        const ulonglong2* shWc = reinterpret_cast<const ulonglong2*>(shW[parity]);
        const ulonglong2* shxc = reinterpret_cast<const ulonglong2*>(shx[parity]);

        #pragma unroll
        for (int j = 0; j < ITILE; j++) {
            ulonglong2 xa0 = shxc[(j * NB + b0) * 2 + 0];
            ulonglong2 xb0 = shxc[(j * NB + b0) * 2 + 1];
            ulonglong2 xa1 = shxc[(j * NB + b1) * 2 + 0];
            ulonglong2 xb1 = shxc[(j * NB + b1) * 2 + 1];

            float u0[NO], u1[NO];
            #pragma unroll
            for (int o = 0; o < NO; o++) {
                ulonglong2 wa = shWc[(j * NO + o) * 32 + lane];
                ulonglong2 wb = shWc[(j * NO + o) * 32 + 16 + lane];
                unsigned long long t0 = f2mul(wa.x, xa0.x);
                t0 = f2fma(wa.y, xa0.y, t0);
                t0 = f2fma(wb.x, xb0.x, t0);
                t0 = f2fma(wb.y, xb0.y, t0);
                u0[o] = f2hadd(t0);
                unsigned long long t1 = f2mul(wa.x, xa1.x);
                t1 = f2fma(wa.y, xa1.y, t1);
                t1 = f2fma(wb.x, xb1.x, t1);
                t1 = f2fma(wb.y, xb1.y, t1);
                u1[o] = f2hadd(t1);
            }

            #pragma unroll
            for (int bb = 0; bb < 2; bb++) {
                const float* u  = bb ? u1 : u0;
                const float* vr = bb ? vr1 : vr0;
                float* acc = bb ? acc1 : acc0;

                float p[NO];
                #pragma unroll
                for (int o = 0; o < NO; o++) p[o] = u[o] * vr[o];

                float q[5];
                #pragma unroll
                for (int k = 0; k < 5; k++) {
                    float keep = s8 ? p[2 * k + 1] : p[2 * k];
                    float send = s8 ? p[2 * k] : p[2 * k + 1];
                    q[k] = keep + __shfl_xor_sync(0xffffffffu, send, 8, 16);
                }
                float r0, r1, r2;
                {
                    float keep = s4 ? q[1] : q[0];
                    float send = s4 ? q[0] : q[1];
                    r0 = keep + __shfl_xor_sync(0xffffffffu, send, 4, 16);
                }
                {
                    float keep = s4 ? q[3] : q[2];
                    float send = s4 ? q[2] : q[3];
                    r1 = keep + __shfl_xor_sync(0xffffffffu, send, 4, 16);
                }
                r2 = q[4] + __shfl_xor_sync(0xffffffffu, q[4], 4, 16);
                float t0, t1;
                {
                    float keep = s2 ? r1 : r0;
                    float send = s2 ? r0 : r1;
                    t0 = keep + __shfl_xor_sync(0xffffffffu, send, 2, 16);
                }
                t1 = r2 + __shfl_xor_sync(0xffffffffu, r2, 2, 16);
                float a;
                {
                    float keep = s1 ? t1 : t0;
                    float send = s1 ? t0 : t1;
                    a = keep + __shfl_xor_sync(0xffffffffu, send, 1, 16);
                }

                float e = __expf(a);
                float m = validLane ? e : 0.f;
                m += __shfl_xor_sync(0xffffffffu, m, 8, 16);
                m += __shfl_xor_sync(0xffffffffu, m, 4, 16);
                m += __shfl_xor_sync(0xffffffffu, m, 2, 16);
                m += __shfl_xor_sync(0xffffffffu, m, 1, 16);
                float c_self = __fdividef(e, m);

                acc[0] = fmaf(__shfl_sync(0xffffffffu, c_self, 0, 16),  u[0], acc[0]);
                acc[1] = fmaf(__shfl_sync(0xffffffffu, c_self, 8, 16),  u[1], acc[1]);
                acc[2] = fmaf(__shfl_sync(0xffffffffu, c_self, 4, 16),  u[2], acc[2]);
                acc[3] = fmaf(__shfl_sync(0xffffffffu, c_self, 12, 16), u[3], acc[3]);
                acc[4] = fmaf(__shfl_sync(0xffffffffu, c_self, 2, 16),  u[4], acc[4]);
                acc[5] = fmaf(__shfl_sync(0xffffffffu, c_self, 10, 16), u[5], acc[5]);
                acc[6] = fmaf(__shfl_sync(0xffffffffu, c_self, 6, 16),  u[6], acc[6]);
                acc[7] = fmaf(__shfl_sync(0xffffffffu, c_self, 14, 16), u[7], acc[7]);
                acc[8] = fmaf(__shfl_sync(0xffffffffu, c_self, 1, 16),  u[8], acc[8]);
                acc[9] = fmaf(__shfl_sync(0xffffffffu, c_self, 9, 16),  u[9], acc[9]);
            }
        }
        parity = (parity + 1 == 3) ? 0 : parity + 1;
    }

    #pragma unroll
    for (int o = 0; o < NO; o++) {
        atomicAdd(&g_s[(b0 * NO + o) * ND + lane], acc0[o]);
        atomicAdd(&g_s[(b1 * NO + o) * ND + lane], acc1[o]);
    }

    squash_epilogue<ITER>(tid, out);
}

extern "C" void kernel_launch(void* const* d_in, const int* in_sizes, int n_in,
                              void* d_out, int out_size)
{
    const float* x = (const float*)d_in[0];  // [64, 8000, 8]
    const float* W = (const float*)d_in[1];  // [10, 8000, 16, 8]
    float* out = (float*)d_out;              // [64, 10, 16]

    pass0_kernel<<<NBLK, NTHR>>>(x, W, out);    // uniform c=0.1 (in prescale)
    pass_kernel<1><<<NBLK, NTHR>>>(x, W, out);  // c = softmax_o(u.v0)
    pass_kernel<2><<<NBLK, NTHR>>>(x, W, out);  // c = softmax_o(u.(v0+v1))
}

// round 10
// speedup vs baseline: 1.3147x; 1.0270x over previous
#include <cuda_runtime.h>
#include <cstdint>

#define NB 64
#define NO 10
#define NI 8000
#define ND 16
#define NE 8

#define ITILE 2
#define NTHR 512
#define NSTAGES (NI / ITILE)     // 4000 stages of 2 i's

#define NWITEM (ITILE * NO * 32) // 640 W float4 per stage
#define NXITEM (ITILE * NB * 2)  // 256 x float4 per stage
#define WBUFB (NWITEM * 16)      // 10240 B per W buffer
#define XBUFB (NXITEM * 16)      // 4096 B per x buffer

#define NBLK 148                 // 1 block/SM, one full wave
#define STEPI (NBLK * ITILE)     // i0 advance per grid-stride step = 296

// Scratch (no allocation allowed). g_s zeroed by the fused squash each pass,
// g_ticket reset by the last block -> graph replays are deterministic.
__device__ float g_s[NB * NO * ND] = {};
__device__ float g_v[NB * NO * ND] = {};
__device__ float g_vsum[NB * NO * ND] = {};
__device__ unsigned int g_ticket = 0;

// ---- f32x2 packed math (sm_10x; ptxas won't auto-fuse, must be PTX) ----
__device__ __forceinline__ unsigned long long f2mul(unsigned long long a, unsigned long long b) {
    unsigned long long d;
    asm("mul.rn.f32x2 %0, %1, %2;" : "=l"(d) : "l"(a), "l"(b));
    return d;
}
__device__ __forceinline__ unsigned long long f2fma(unsigned long long a, unsigned long long b, unsigned long long c) {
    unsigned long long d;
    asm("fma.rn.f32x2 %0, %1, %2, %3;" : "=l"(d) : "l"(a), "l"(b), "l"(c));
    return d;
}
__device__ __forceinline__ float f2hadd(unsigned long long a) {
    float lo, hi;
    asm("mov.b64 {%0, %1}, %2;" : "=f"(lo), "=f"(hi) : "l"(a));
    return lo + hi;
}

// ---- cp.async (LDGSTS) helpers ----
__device__ __forceinline__ void cp16(uint32_t dst, const void* src) {
    asm volatile("cp.async.ca.shared.global [%0], [%1], 16;" :: "r"(dst), "l"(src));
}
__device__ __forceinline__ void cp_commit() { asm volatile("cp.async.commit_group;"); }
template <int N>
__device__ __forceinline__ void cp_wait() { asm volatile("cp.async.wait_group %0;" :: "n"(N)); }
__device__ __forceinline__ uint32_t sptr(const void* p) {
    return (uint32_t)__cvta_generic_to_shared(p);
}

// ---- shared staging descriptor (same smem image for all passes) ----
// shW per (j,o): 32 float4, idx qs = e4*16 + d. shx per (j,b): 2 float4.
struct Stager {
    const float4* srcA;
    const float4* srcB;
    uint32_t dstA0, dstB0, bufStrB;
    int srcStepB;
    bool hasB;

    __device__ __forceinline__ void init(int tid, int i00,
                                         const float4* Wf4, const float4* xf4,
                                         uint32_t swbase, uint32_t sxbase) {
        {
            int t = tid;                           // W item < 640
            int j  = t / (NO * 32);
            int r  = t - j * (NO * 32);
            int o  = r >> 5;
            int qg = r & 31;                       // global: d*2 + e4
            int qs = ((qg & 1) << 4) | (qg >> 1);  // shared: e4*16 + d
            srcA  = Wf4 + ((size_t)o * NI + i00 + j) * 32 + qg;
            dstA0 = swbase + (uint32_t)((j * NO + o) * 32 + qs) * 16u;
        }
        hasB = (tid < 384);
        srcB = Wf4; dstB0 = swbase; srcStepB = 0; bufStrB = 0;
        if (tid < 128) {            // W item t = tid+512 in [512,640)
            int t = tid + 512;
            int j  = t / (NO * 32);
            int r  = t - j * (NO * 32);
            int o  = r >> 5;
            int qg = r & 31;
            int qs = ((qg & 1) << 4) | (qg >> 1);
            srcB  = Wf4 + ((size_t)o * NI + i00 + j) * 32 + qg;
            dstB0 = swbase + (uint32_t)((j * NO + o) * 32 + qs) * 16u;
            srcStepB = 32 * STEPI;
            bufStrB  = WBUFB;
        } else if (tid < 384) {     // x item v = tid-128 in [0,256)
            int v = tid - 128;
            int j = v >> 7;
            int r = v & 127;
            int bb = r >> 1;
            int q  = r & 1;
            srcB  = xf4 + ((size_t)bb * NI + i00 + j) * 2 + q;
            dstB0 = sxbase + (uint32_t)((j * NB + bb) * 2 + q) * 16u;
            srcStepB = 2 * STEPI;
            bufStrB  = XBUFB;
        }
    }
    __device__ __forceinline__ void issue(int ib) {
        cp16(dstA0 + (uint32_t)ib * WBUFB, srcA);
        srcA += 32 * STEPI;
        if (hasB) {
            cp16(dstB0 + (uint32_t)ib * bufStrB, srcB);
            srcB += srcStepB;
        }
        cp_commit();
    }
};

// ---- fused squash epilogue (last block), shared by all passes ----
template <int ITER>
__device__ __forceinline__ void squash_epilogue(int tid, float* __restrict__ out)
{
    __threadfence();
    __shared__ unsigned int lastFlag;
    if (tid == 0)
        lastFlag = (atomicAdd(&g_ticket, 1u) == (unsigned)(NBLK - 1)) ? 1u : 0u;
    __syncthreads();
    if (!lastFlag) return;
    __threadfence();  // acquire: all other blocks' atomics are visible

    const float prescale = (ITER == 0) ? 0.1f : 1.0f;
    #pragma unroll
    for (int k = 0; k < (NB * NO * ND) / NTHR; k++) {
        int idx = k * NTHR + tid;            // idx & 15 == d-lane
        float val = g_s[idx] * prescale;
        g_s[idx] = 0.f;
        float n2 = val * val;
        n2 += __shfl_xor_sync(0xffffffffu, n2, 8, 16);
        n2 += __shfl_xor_sync(0xffffffffu, n2, 4, 16);
        n2 += __shfl_xor_sync(0xffffffffu, n2, 2, 16);
        n2 += __shfl_xor_sync(0xffffffffu, n2, 1, 16);
        float norm  = sqrtf(n2);
        float scale = n2 / ((1.f + n2) * (norm + 1e-8f));
        float v = scale * val;
        if (ITER == 0)      { g_v[idx] = v; g_vsum[idx] = v; }
        else if (ITER == 1) { g_v[idx] = v; g_vsum[idx] += v; }
        else                { out[idx] = v; }
    }
    if (tid == 0) g_ticket = 0;  // reset for next pass / next graph replay
}

// ============ PASS 0: pure split-K GEMM, (4 batch, 5 o) per thread ============
__global__ void __launch_bounds__(NTHR, 1)
pass0_kernel(const float* __restrict__ xg, const float* __restrict__ Wg,
             float* __restrict__ out)
{
    __shared__ float4 shW[3][NWITEM];  // 3 x 10 KB
    __shared__ float4 shx[3][NXITEM];  // 3 x 4 KB

    const int tid  = threadIdx.x;
    const int lane = tid & 15;        // d
    const int grp  = tid >> 4;        // 0..31
    const int quad = grp >> 1;        // 0..15 -> batches 4q..4q+3
    const int ob   = (grp & 1) * 5;   // o-half base: 0 or 5

    unsigned long long accp[4][5];
    #pragma unroll
    for (int bb = 0; bb < 4; bb++)
        #pragma unroll
        for (int o = 0; o < 5; o++) accp[bb][o] = 0ull;

    const float4* Wf4 = (const float4*)Wg;
    const float4* xf4 = (const float4*)xg;

    Stager sg;
    sg.init(tid, blockIdx.x * ITILE, Wf4, xf4, sptr(&shW[0][0]), sptr(&shx[0][0]));

    const int st0 = blockIdx.x;
    sg.issue(0);
    if (st0 + NBLK < NSTAGES) sg.issue(1); else cp_commit();

    int parity = 0, inext = 2;
    for (int st = st0; st < NSTAGES; st += NBLK) {
        cp_wait<1>();
        __syncthreads();
        if (st + 2 * NBLK < NSTAGES) sg.issue(inext); else cp_commit();
        inext = (inext + 1 == 3) ? 0 : inext + 1;

        const ulonglong2* shWc = reinterpret_cast<const ulonglong2*>(shW[parity]);
        const ulonglong2* shxc = reinterpret_cast<const ulonglong2*>(shx[parity]);

        #pragma unroll
        for (int j = 0; j < ITILE; j++) {
            ulonglong2 xa[4], xb[4];
            #pragma unroll
            for (int bb = 0; bb < 4; bb++) {
                xa[bb] = shxc[(j * NB + quad * 4 + bb) * 2 + 0];  // e0..3
                xb[bb] = shxc[(j * NB + quad * 4 + bb) * 2 + 1];  // e4..7
            }
            #pragma unroll
            for (int o = 0; o < 5; o++) {
                const int og = ob + o;
                ulonglong2 wa = shWc[(j * NO + og) * 32 + lane];       // e0..3
                ulonglong2 wb = shWc[(j * NO + og) * 32 + 16 + lane];  // e4..7
                #pragma unroll
                for (int bb = 0; bb < 4; bb++) {
                    accp[bb][o] = f2fma(wa.x, xa[bb].x, accp[bb][o]);
                    accp[bb][o] = f2fma(wa.y, xa[bb].y, accp[bb][o]);
                    accp[bb][o] = f2fma(wb.x, xb[bb].x, accp[bb][o]);
                    accp[bb][o] = f2fma(wb.y, xb[bb].y, accp[bb][o]);
                }
            }
        }
        parity = (parity + 1 == 3) ? 0 : parity + 1;
    }

    #pragma unroll
    for (int bb = 0; bb < 4; bb++)
        #pragma unroll
        for (int o = 0; o < 5; o++)
            atomicAdd(&g_s[((quad * 4 + bb) * NO + ob + o) * ND + lane],
                      f2hadd(accp[bb][o]));

    squash_epilogue<0>(tid, out);
}

// ============ ROUTED PASSES (ITER 1/2): o-split layout ============
// Warp = 4 batches (4*wid .. 4*wid+3). Half-warp selects o-half:
// lanes 0-15 -> o in [0,5), lanes 16-31 -> o in [5,10); d = lane & 15.
// All 32 lanes read DISTINCT W addresses; each staged W value feeds 4
// batches (W crossbar traffic halves vs the 2-batch layout). Routing tree
// runs on 5 arrays per half (both halves process the same batch's two
// o-halves simultaneously): o(l) = s2 ? 4 : 2*s4 + s8 (local), owners
// {o0..o4} -> lanes {0,8,4,12,2}; softmax denom = masked width-32 butterfly.
template <int ITER>
__global__ void __launch_bounds__(NTHR, 1)
pass_kernel(const float* __restrict__ xg, const float* __restrict__ Wg,
            float* __restrict__ out)
{
    __shared__ float4 shW[3][NWITEM];
    __shared__ float4 shx[3][NXITEM];

    const int tid  = threadIdx.x;
    const int wid  = tid >> 5;        // warp 0..15
    const int l32  = tid & 31;
    const int d    = tid & 15;        // d-lane
    const int ob   = (l32 >> 4) * 5;  // o-half base: 0 or 5
    const int bq   = wid * 4;         // batch base

    const bool s8 = (d & 8) != 0;
    const bool s4 = (d & 4) != 0;
    const bool s2 = (d & 2) != 0;
    const bool s1 = (d & 1) != 0;
    // one lane per o (per half) for the softmax denominator:
    const bool validLane = !s1 && (!s2 || (!s4 && !s8));

    float vr[4][5], acc[4][5];
    {
        const float* vin = (ITER == 1) ? g_v : g_vsum;
        #pragma unroll
        for (int bb = 0; bb < 4; bb++)
            #pragma unroll
            for (int o = 0; o < 5; o++) {
                vr[bb][o] = vin[((bq + bb) * NO + ob + o) * ND + d];
                acc[bb][o] = 0.f;
            }
    }

    const float4* Wf4 = (const float4*)Wg;
    const float4* xf4 = (const float4*)xg;

    Stager sg;
    sg.init(tid, blockIdx.x * ITILE, Wf4, xf4, sptr(&shW[0][0]), sptr(&shx[0][0]));

    const int st0 = blockIdx.x;
    sg.issue(0);
    if (st0 + NBLK < NSTAGES) sg.issue(1); else cp_commit();

    int parity = 0, inext = 2;
    for (int st = st0; st < NSTAGES; st += NBLK) {
        cp_wait<1>();
        __syncthreads();
        if (st + 2 * NBLK < NSTAGES) sg.issue(inext); else cp_commit();
        inext = (inext + 1 == 3) ? 0 : inext + 1;

        const ulonglong2* shWc = reinterpret_cast<const ulonglong2*>(shW[parity]);
        const ulonglong2* shxc = reinterpret_cast<const ulonglong2*>(shx[parity]);

        #pragma unroll
        for (int j = 0; j < ITILE; j++) {
            ulonglong2 xa[4], xb[4];
            #pragma unroll
            for (int bb = 0; bb < 4; bb++) {
                xa[bb] = shxc[(j * NB + bq + bb) * 2 + 0];  // e0..3
                xb[bb] = shxc[(j * NB + bq + bb) * 2 + 1];  // e4..7
            }

            // u[bb][oo] for this half's 5 o's, 4 batches
            float u[4][5];
            #pragma unroll
            for (int oo = 0; oo < 5; oo++) {
                const int og = ob + oo;
                ulonglong2 wa = shWc[(j * NO + og) * 32 + d];
                ulonglong2 wb = shWc[(j * NO + og) * 32 + 16 + d];
                #pragma unroll
                for (int bb = 0; bb < 4; bb++) {
                    unsigned long long t = f2mul(wa.x, xa[bb].x);
                    t = f2fma(wa.y, xa[bb].y, t);
                    t = f2fma(wb.x, xb[bb].x, t);
                    t = f2fma(wb.y, xb[bb].y, t);
                    u[bb][oo] = f2hadd(t);
                }
            }

            // routing per batch: both halves handle their own 5 o's in SIMD
            #pragma unroll
            for (int bb = 0; bb < 4; bb++) {
                float p[5];
                #pragma unroll
                for (int oo = 0; oo < 5; oo++) p[oo] = u[bb][oo] * vr[bb][oo];

                // pairing tree over 16 d-lanes, 5 arrays -> 7 SHFL
                float q0, q1, q2;
                {
                    float keep = s8 ? p[1] : p[0];
                    float send = s8 ? p[0] : p[1];
                    q0 = keep + __shfl_xor_sync(0xffffffffu, send, 8, 16);
                }
                {
                    float keep = s8 ? p[3] : p[2];
                    float send = s8 ? p[2] : p[3];
                    q1 = keep + __shfl_xor_sync(0xffffffffu, send, 8, 16);
                }
                q2 = p[4] + __shfl_xor_sync(0xffffffffu, p[4], 8, 16);
                float r0, r1;
                {
                    float keep = s4 ? q1 : q0;
                    float send = s4 ? q0 : q1;
                    r0 = keep + __shfl_xor_sync(0xffffffffu, send, 4, 16);
                }
                r1 = q2 + __shfl_xor_sync(0xffffffffu, q2, 4, 16);
                float t0;
                {
                    float keep = s2 ? r1 : r0;
                    float send = s2 ? r0 : r1;
                    t0 = keep + __shfl_xor_sync(0xffffffffu, send, 2, 16);
                }
                float a = t0 + __shfl_xor_sync(0xffffffffu, t0, 1, 16);
                // lane holds a[o], o = s2 ? 4 : 2*s4+s8 (within its half)

                // softmax denom over ALL 10 o's: masked width-32 butterfly
                float e = __expf(a);
                float m = validLane ? e : 0.f;
                m += __shfl_xor_sync(0xffffffffu, m, 16);
                m += __shfl_xor_sync(0xffffffffu, m, 8);
                m += __shfl_xor_sync(0xffffffffu, m, 4);
                m += __shfl_xor_sync(0xffffffffu, m, 2);
                m += __shfl_xor_sync(0xffffffffu, m, 1);
                float c_self = __fdividef(e, m);

                // broadcast c for this half's o's from owner lanes (width 16)
                acc[bb][0] = fmaf(__shfl_sync(0xffffffffu, c_self, 0, 16),  u[bb][0], acc[bb][0]);
                acc[bb][1] = fmaf(__shfl_sync(0xffffffffu, c_self, 8, 16),  u[bb][1], acc[bb][1]);
                acc[bb][2] = fmaf(__shfl_sync(0xffffffffu, c_self, 4, 16),  u[bb][2], acc[bb][2]);
                acc[bb][3] = fmaf(__shfl_sync(0xffffffffu, c_self, 12, 16), u[bb][3], acc[bb][3]);
                acc[bb][4] = fmaf(__shfl_sync(0xffffffffu, c_self, 2, 16),  u[bb][4], acc[bb][4]);
            }
        }
        parity = (parity + 1 == 3) ? 0 : parity + 1;
    }

    #pragma unroll
    for (int bb = 0; bb < 4; bb++)
        #pragma unroll
        for (int oo = 0; oo < 5; oo++)
            atomicAdd(&g_s[((bq + bb) * NO + ob + oo) * ND + d], acc[bb][oo]);

    squash_epilogue<ITER>(tid, out);
}

extern "C" void kernel_launch(void* const* d_in, const int* in_sizes, int n_in,
                              void* d_out, int out_size)
{
    const float* x = (const float*)d_in[0];  // [64, 8000, 8]
    const float* W = (const float*)d_in[1];  // [10, 8000, 16, 8]
    float* out = (float*)d_out;              // [64, 10, 16]

    pass0_kernel<<<NBLK, NTHR>>>(x, W, out);    // uniform c=0.1 (in prescale)
    pass_kernel<1><<<NBLK, NTHR>>>(x, W, out);  // c = softmax_o(u.v0)
    pass_kernel<2><<<NBLK, NTHR>>>(x, W, out);  // c = softmax_o(u.(v0+v1))
}